// round 15
// baseline (speedup 1.0000x reference)
#include <cuda_runtime.h>

// NeighborList: all i<j pairs, minimum-image PBC, cutoff mask. Single fused kernel.
// Output (float32): [0,P) pair_i | [P,2P) pair_j | [2P,5P) deltas[P,3] | [5P,6P) dist

#define TPB      256
#define KITER    4
#define BLKPAIRS (TPB * KITER)     // 1024 j's per block
#define TILE_F   (3 * BLKPAIRS + 4) // tile floats (+4 for float4 alignment slack)

__device__ __forceinline__ float fast_sqrt(float x) {
    float r;
    asm("sqrt.approx.f32 %0, %1;" : "=f"(r) : "f"(x));
    return r;
}

// Row-block mapping: blockIdx.y = row i; block covers BLKPAIRS consecutive j's.
// j-atoms staged into smem via float4 copy; cell classified once by tid 0 into
// smem scalars (keeps per-thread register pressure at the R13 level).
__global__ void __launch_bounds__(TPB)
nl_kernel(const float* __restrict__ xyz, const float* __restrict__ cell,
          float* __restrict__ out, int n, unsigned P) {
    const int i     = blockIdx.y;
    const int len   = n - 1 - i;                 // pairs in this row
    const int start = blockIdx.x * BLKPAIRS;     // offset within row
    if (start >= len) return;                    // empty block: fast exit

    const bool full = (start + BLKPAIRS) <= len; // uniform: interior block

    const unsigned T    = 2u * (unsigned)n - 1u;
    const unsigned offi = ((unsigned)i * (T - (unsigned)i)) >> 1;

    const int tid = threadIdx.x;

    __shared__ float stile[TILE_F];
    __shared__ float scell[7];   // d0,d4,d8,e0,e4,e8,general

    // ---- float4 tile copy: floats [base, base+3072) of xyz, base rounded
    //      down to a float4 boundary (off in [0,3] folded into indices) ----
    const int base  = 3 * (i + 1 + start);
    const int base4 = base & ~3;
    const int off   = base - base4;
    {
        const float4* src = reinterpret_cast<const float4*>(xyz);
        float4* dst = reinterpret_cast<float4*>(stile);
        const int v0   = base4 >> 2;
        const int vmax = (3 * n - 4) >> 2;       // last valid float4 index
#pragma unroll
        for (int q = 0; q < 3; q++) {            // 768 float4s = 3072 floats
            int vidx = v0 + q * TPB + tid;
            if (vidx > vmax) vidx = vmax;        // clamp: dup reads, masked later
            dst[q * TPB + tid] = src[vidx];
        }
        if (tid == 0) {                          // remainder float4 (when off>0)
            int vidx = v0 + 3 * TPB;
            if (vidx > vmax) vidx = vmax;
            dst[3 * TPB] = src[vidx];
        }
    }

    // ---- cell classification once per block ----
    if (tid == 0) {
        const float c0 = cell[0], c1 = cell[1], c2 = cell[2];
        const float c3 = cell[3], c4 = cell[4], c5 = cell[5];
        const float c6 = cell[6], c7 = cell[7], c8 = cell[8];
        const bool zero = (c0 == 0.f) && (c1 == 0.f) && (c2 == 0.f) &&
                          (c3 == 0.f) && (c4 == 0.f) && (c5 == 0.f) &&
                          (c6 == 0.f) && (c7 == 0.f) && (c8 == 0.f);
        const bool offz = (c1 == 0.f) && (c2 == 0.f) && (c3 == 0.f) &&
                          (c5 == 0.f) && (c6 == 0.f) && (c7 == 0.f);
        float d0 = 0.f, d4 = 0.f, d8 = 0.f, e0 = 0.f, e4 = 0.f, e8 = 0.f;
        if (!zero && offz) {
            // adjugate inverse with exact zero off-diagonals (bit-identical)
            const float invdet = 1.0f / (c0 * (c4 * c8));
            d0 = (c4 * c8) * invdet;
            d4 = (c0 * c8) * invdet;
            d8 = (c0 * c4) * invdet;
            e0 = c0; e4 = c4; e8 = c8;
        }
        scell[0] = d0; scell[1] = d4; scell[2] = d8;
        scell[3] = e0; scell[4] = e4; scell[5] = e8;
        scell[6] = (!zero && !offz) ? 1.0f : 0.0f;
    }
    __syncthreads();

    const float d0 = scell[0], d4 = scell[1], d8 = scell[2];
    const float e0 = scell[3], e4 = scell[4], e8 = scell[5];
    const int general = (scell[6] != 0.0f);

    // row atom (uniform broadcast)
    const float xi = __ldg(&xyz[3 * i + 0]);
    const float yi = __ldg(&xyz[3 * i + 1]);
    const float zi = __ldg(&xyz[3 * i + 2]);
    const float fi = (float)i;

    int jo = start + tid;                        // pair offset within row
    const size_t p0 = (size_t)offi + (size_t)jo;
    float* pi = out + p0;
    float* pj = out + (size_t)P + p0;
    float* pd = out + 5 * (size_t)P + p0;
    float* db = out + 2 * (size_t)P + 3 * p0;
    int slj = off + 3 * tid;                     // smem index of this thread's j

#pragma unroll
    for (int k = 0; k < KITER; k++) {
        if (!full && jo >= len) break;           // tail block only
        const int j = i + 1 + jo;

        float dx = xi - stile[slj + 0];          // stride-3 LDS: conflict-free
        float dy = yi - stile[slj + 1];
        float dz = zi - stile[slj + 2];

        if (!general) {
            // diagonal (or no) PBC: per-axis wrap; zeros => exact no-op
            dx -= rintf(dx * d0) * e0;           // jnp.round = half-to-even = rintf
            dy -= rintf(dy * d4) * e4;
            dz -= rintf(dz * d8) * e8;
        } else {
            // rare general cell: recompute inverse per pair from volatile loads
            volatile const float* vc = cell;
            const float a = vc[0], b = vc[1], cc = vc[2];
            const float d = vc[3], e = vc[4], f  = vc[5];
            const float g = vc[6], h = vc[7], ii = vc[8];
            const float A =  (e * ii - f * h);
            const float B = -(d * ii - f * g);
            const float C =  (d * h - e * g);
            const float invdet = 1.0f / (a * A + b * B + cc * C);
            const float i0 = A * invdet, i1 = -(b * ii - cc * h) * invdet,
                        i2 = (b * f - cc * e) * invdet;
            const float i3 = B * invdet, i4 =  (a * ii - cc * g) * invdet,
                        i5 = -(a * f - cc * d) * invdet;
            const float i6 = C * invdet, i7 = -(a * h - b * g) * invdet,
                        i8 = (a * e - b * d) * invdet;
            const float f0 = dx * i0 + dy * i3 + dz * i6;
            const float f1 = dx * i1 + dy * i4 + dz * i7;
            const float f2 = dx * i2 + dy * i5 + dz * i8;
            const float r0 = rintf(f0);
            const float r1 = rintf(f1);
            const float r2 = rintf(f2);
            dx -= r0 * a  + r1 * d  + r2 * g;
            dy -= r0 * b  + r1 * e  + r2 * h;
            dz -= r0 * cc + r1 * f  + r2 * ii;
        }

        const float dist = fast_sqrt(dx * dx + dy * dy + dz * dz);
        const bool m = (dist <= 5.0f);

        *pi = m ? fi : -1.0f;
        *pj = m ? (float)j : -1.0f;
        *pd = m ? dist : 0.0f;
        db[0] = m ? dx : 0.0f;                   // lane-consecutive scalar stores
        db[1] = m ? dy : 0.0f;
        db[2] = m ? dz : 0.0f;

        pi += TPB; pj += TPB; pd += TPB; db += 3 * TPB;
        jo += TPB; slj += 3 * TPB;
    }
}

extern "C" void kernel_launch(void* const* d_in, const int* in_sizes, int n_in,
                              void* d_out, int out_size) {
    const float* xyz  = (const float*)d_in[0];
    const float* cell = (const float*)d_in[1];
    if (n_in >= 2 && in_sizes[0] == 9 && in_sizes[1] != 9) {
        const float* t = xyz; xyz = cell; cell = t;
    }
    const int n = (in_sizes[0] == 9 && n_in >= 2) ? in_sizes[1] / 3 : in_sizes[0] / 3;
    const unsigned P = (unsigned)((size_t)n * (size_t)(n - 1) / 2);

    const int maxlen = n - 1;
    dim3 grid((maxlen + BLKPAIRS - 1) / BLKPAIRS, n - 1);
    nl_kernel<<<grid, TPB>>>(xyz, cell, (float*)d_out, n, P);
}